// round 1
// baseline (speedup 1.0000x reference)
#include <cuda_runtime.h>

#define NV 768
#define CV 256
#define KP 272   // 259 channels (256 feat + 3 coord) padded to 17*16

// Scratch (device globals: allocation-free)
__device__ float g_fin[NV * CV];   // f_input
__device__ float g_u[NV * KP];     // fc_w0 * f_input  (+ coord part, zero-padded)
__device__ float g_v[NV * KP];     // fc_w1 * f_input + fc_b (+ coord part)
__device__ float g_P[NV];          // sum_c lw[c]*u[i][c]
__device__ float g_Q[NV];          // sum_c lw[c]*v[i][c]
__device__ float g_lwp[KP];        // 0.4 * lin_w, zero-padded
__device__ float g_att[NV * NV];   // scores, then attention (in place)

// ---------------------------------------------------------------------------
// Kernel 1: f_input = features @ FC.  4 rows per block, 256 threads.
// ---------------------------------------------------------------------------
__global__ void k_fin(const float* __restrict__ feat, const float* __restrict__ FCm) {
    __shared__ float sf[4][CV];
    const int i0 = blockIdx.x * 4;
    const int t  = threadIdx.x;            // 0..255 = output column
    #pragma unroll
    for (int r = 0; r < 4; r++) sf[r][t] = feat[(i0 + r) * CV + t];
    __syncthreads();

    float a0 = 0.f, a1 = 0.f, a2 = 0.f, a3 = 0.f;
    #pragma unroll 8
    for (int k = 0; k < CV; k++) {
        float w = FCm[k * CV + t];
        a0 = fmaf(sf[0][k], w, a0);
        a1 = fmaf(sf[1][k], w, a1);
        a2 = fmaf(sf[2][k], w, a2);
        a3 = fmaf(sf[3][k], w, a3);
    }
    g_fin[(i0 + 0) * CV + t] = a0;
    g_fin[(i0 + 1) * CV + t] = a1;
    g_fin[(i0 + 2) * CV + t] = a2;
    g_fin[(i0 + 3) * CV + t] = a3;
}

// ---------------------------------------------------------------------------
// Kernel 2: per-row prep. u, v, P, Q, lwp. One block per row.
// ---------------------------------------------------------------------------
__global__ void k_prep(const float* __restrict__ coord,
                       const float* __restrict__ fc_w, const float* __restrict__ fc_b,
                       const float* __restrict__ sc_w, const float* __restrict__ sc_b,
                       const float* __restrict__ lin_w) {
    const int i = blockIdx.x;
    const int t = threadIdx.x;   // 256
    const float w0 = fc_w[0], w1 = fc_w[1], bf = fc_b[0];

    float f = g_fin[i * CV + t];
    float u = w0 * f;
    float v = fmaf(w1, f, bf);
    g_u[i * KP + t] = u;
    g_v[i * KP + t] = v;

    float lw = lin_w[t];
    float pu = lw * u;
    float pv = lw * v;

    if (t < KP - CV) {                // t < 16 handles channels 256..271
        int c2 = CV + t;
        float uu = 0.f, vv = 0.f, lw2 = 0.f;
        if (c2 < CV + 3) {
            float cd = coord[i * 3 + t];
            uu  = sc_w[0] * cd;
            vv  = fmaf(sc_w[1], cd, sc_b[0]);
            lw2 = lin_w[c2];
        }
        g_u[i * KP + c2] = uu;
        g_v[i * KP + c2] = vv;
        pu = fmaf(lw2, uu, pu);
        pv = fmaf(lw2, vv, pv);
    }

    if (i == 0) {                     // one block writes the scaled lin_w
        g_lwp[t] = 0.4f * lin_w[t];
        if (t < KP - CV) {
            int c2 = CV + t;
            g_lwp[c2] = (c2 < CV + 3) ? 0.4f * lin_w[c2] : 0.f;
        }
    }

    __shared__ float rp[256], rq[256];
    rp[t] = pu; rq[t] = pv;
    __syncthreads();
    #pragma unroll
    for (int s = 128; s > 0; s >>= 1) {
        if (t < s) { rp[t] += rp[t + s]; rq[t] += rq[t + s]; }
        __syncthreads();
    }
    if (t == 0) { g_P[i] = rp[0]; g_Q[i] = rq[0]; }
}

// ---------------------------------------------------------------------------
// Kernel 3: scores tile kernel. 64x64 tile, 256 threads, 4x4 micro (stride 16).
// score(i,j) = leaky( 0.6*(P_i+Q_j) + lin_b + sum_c lwp[c]*|u_i[c]+v_j[c]| )
// ---------------------------------------------------------------------------
__global__ void k_scores(const float* __restrict__ lin_b) {
    __shared__ float su[64][17];
    __shared__ float sv[64][17];
    __shared__ float slw[16];

    const int tid = threadIdx.x;          // 256
    const int tx = tid & 15;              // j direction
    const int ty = tid >> 4;              // i direction
    const int i0 = blockIdx.y * 64;
    const int j0 = blockIdx.x * 64;

    float acc[4][4];
    #pragma unroll
    for (int k = 0; k < 4; k++)
        #pragma unroll
        for (int m = 0; m < 4; m++) acc[k][m] = 0.f;

    for (int k0 = 0; k0 < KP; k0 += 16) {
        #pragma unroll
        for (int l = 0; l < 4; l++) {
            int idx = tid + l * 256;          // 0..1023
            int r  = idx >> 4;
            int cc = idx & 15;
            su[r][cc] = g_u[(i0 + r) * KP + k0 + cc];
            sv[r][cc] = g_v[(j0 + r) * KP + k0 + cc];
        }
        if (tid < 16) slw[tid] = g_lwp[k0 + tid];
        __syncthreads();

        #pragma unroll
        for (int cc = 0; cc < 16; cc++) {
            float w = slw[cc];
            float a[4], b[4];
            #pragma unroll
            for (int k = 0; k < 4; k++) a[k] = su[ty + k * 16][cc];
            #pragma unroll
            for (int m = 0; m < 4; m++) b[m] = sv[tx + m * 16][cc];
            #pragma unroll
            for (int k = 0; k < 4; k++)
                #pragma unroll
                for (int m = 0; m < 4; m++) {
                    float tval = a[k] + b[m];
                    acc[k][m] = fmaf(w, fmaxf(tval, -tval), acc[k][m]);
                }
        }
        __syncthreads();
    }

    const float lb = lin_b[0];
    float Pi[4], Qj[4];
    #pragma unroll
    for (int k = 0; k < 4; k++) Pi[k] = g_P[i0 + ty + k * 16];
    #pragma unroll
    for (int m = 0; m < 4; m++) Qj[m] = g_Q[j0 + tx + m * 16];

    #pragma unroll
    for (int k = 0; k < 4; k++) {
        int i = i0 + ty + k * 16;
        #pragma unroll
        for (int m = 0; m < 4; m++) {
            int j = j0 + tx + m * 16;
            float s = fmaf(0.6f, Pi[k] + Qj[m], lb) + acc[k][m];
            g_att[i * NV + j] = fmaxf(s, 0.2f * s);   // leaky(0.2)
        }
    }
}

// ---------------------------------------------------------------------------
// Kernel 4: row softmax (in place in g_att). One block per row, 256 threads.
// ---------------------------------------------------------------------------
__global__ void k_softmax() {
    const int i = blockIdx.x;
    const int t = threadIdx.x;
    __shared__ float red[256];

    float x0 = g_att[i * NV + t];
    float x1 = g_att[i * NV + t + 256];
    float x2 = g_att[i * NV + t + 512];

    float m = fmaxf(x0, fmaxf(x1, x2));
    red[t] = m;
    __syncthreads();
    #pragma unroll
    for (int s = 128; s > 0; s >>= 1) {
        if (t < s) red[t] = fmaxf(red[t], red[t + s]);
        __syncthreads();
    }
    float mx = red[0];
    __syncthreads();

    float e0 = __expf(x0 - mx);
    float e1 = __expf(x1 - mx);
    float e2 = __expf(x2 - mx);
    red[t] = e0 + e1 + e2;
    __syncthreads();
    #pragma unroll
    for (int s = 128; s > 0; s >>= 1) {
        if (t < s) red[t] += red[t + s];
        __syncthreads();
    }
    float inv = 1.0f / red[0];

    g_att[i * NV + t]       = e0 * inv;
    g_att[i * NV + t + 256] = e1 * inv;
    g_att[i * NV + t + 512] = e2 * inv;
}

// ---------------------------------------------------------------------------
// Kernel 5: out = elu(attention @ f_input). Tile M=32, N=64, 128 threads,
// 4x4 micro with stride-8/stride-16 assignment (conflict-free LDS).
// ---------------------------------------------------------------------------
__global__ void k_out(float* __restrict__ out) {
    __shared__ float sa[32][17];
    __shared__ float sb[16][64];

    const int tid = threadIdx.x;      // 128
    const int tx = tid & 15;          // col direction
    const int ty = tid >> 4;          // 0..7, row direction
    const int i0 = blockIdx.y * 32;
    const int j0 = blockIdx.x * 64;

    float acc[4][4];
    #pragma unroll
    for (int k = 0; k < 4; k++)
        #pragma unroll
        for (int m = 0; m < 4; m++) acc[k][m] = 0.f;

    for (int k0 = 0; k0 < NV; k0 += 16) {
        #pragma unroll
        for (int l = 0; l < 4; l++) {
            int idx = tid + l * 128;      // 0..511
            int r  = idx >> 4;
            int cc = idx & 15;
            sa[r][cc] = g_att[(i0 + r) * NV + k0 + cc];
        }
        #pragma unroll
        for (int l = 0; l < 8; l++) {
            int idx = tid + l * 128;      // 0..1023
            int cc = idx >> 6;
            int n  = idx & 63;
            sb[cc][n] = g_fin[(k0 + cc) * CV + j0 + n];
        }
        __syncthreads();

        #pragma unroll
        for (int cc = 0; cc < 16; cc++) {
            float a[4], b[4];
            #pragma unroll
            for (int k = 0; k < 4; k++) a[k] = sa[ty + k * 8][cc];
            #pragma unroll
            for (int m = 0; m < 4; m++) b[m] = sb[cc][tx + m * 16];
            #pragma unroll
            for (int k = 0; k < 4; k++)
                #pragma unroll
                for (int m = 0; m < 4; m++)
                    acc[k][m] = fmaf(a[k], b[m], acc[k][m]);
        }
        __syncthreads();
    }

    #pragma unroll
    for (int k = 0; k < 4; k++) {
        int i = i0 + ty + k * 8;
        #pragma unroll
        for (int m = 0; m < 4; m++) {
            int j = j0 + tx + m * 16;
            float h = acc[k][m];
            out[i * CV + j] = (h > 0.f) ? h : (__expf(h) - 1.0f);   // ELU
        }
    }
}

// ---------------------------------------------------------------------------
extern "C" void kernel_launch(void* const* d_in, const int* in_sizes, int n_in,
                              void* d_out, int out_size) {
    const float* feat  = (const float*)d_in[0];
    const float* coord = (const float*)d_in[1];
    // d_in[2] = adj (unused by forward)
    const float* FCm   = (const float*)d_in[3];
    const float* fc_w  = (const float*)d_in[4];
    const float* fc_b  = (const float*)d_in[5];
    const float* sc_w  = (const float*)d_in[6];
    const float* sc_b  = (const float*)d_in[7];
    const float* lin_w = (const float*)d_in[8];
    const float* lin_b = (const float*)d_in[9];
    float* out = (float*)d_out;

    k_fin<<<NV / 4, 256>>>(feat, FCm);
    k_prep<<<NV, 256>>>(coord, fc_w, fc_b, sc_w, sc_b, lin_w);
    dim3 gs(NV / 64, NV / 64);
    k_scores<<<gs, 256>>>(lin_b);
    k_softmax<<<NV, 256>>>();
    dim3 go(CV / 64, NV / 32);
    k_out<<<go, 128>>>(out);
}

// round 3
// speedup vs baseline: 1.3700x; 1.3700x over previous
#include <cuda_runtime.h>

#define NV 768
#define CV 256
#define KP 272   // 259 channels (256 feat + 3 coord) padded to 17*16 (even)

typedef unsigned long long ull;

// Scratch (device globals: allocation-free)
__device__ float g_fin[NV * CV];   // f_input
__device__ float g_u[NV * KP];     // fc_w0 * f_input (+ coord part, zero-padded)
__device__ float g_v[NV * KP];     // fc_w1 * f_input + fc_b (+ coord part)
__device__ float g_P[NV];          // sum_c lw[c]*u[i][c]
__device__ float g_Q[NV];          // sum_c lw[c]*v[i][c]
__device__ float g_lwp[KP];        // 0.4 * lin_w, zero-padded
__device__ float g_att[NV * NV];   // scores, then attention (in place)

// ---------------- packed f32x2 helpers (sm_103a) ----------------
__device__ __forceinline__ ull f32x2_add(ull a, ull b) {
    ull r; asm("add.rn.f32x2 %0, %1, %2;" : "=l"(r) : "l"(a), "l"(b)); return r;
}
__device__ __forceinline__ ull f32x2_fma(ull a, ull b, ull c) {
    ull r; asm("fma.rn.f32x2 %0, %1, %2, %3;" : "=l"(r) : "l"(a), "l"(b), "l"(c)); return r;
}
__device__ __forceinline__ ull f32x2_abs(ull a) { return a & 0x7FFFFFFF7FFFFFFFULL; }
__device__ __forceinline__ ull f32x2_dup(float v) {
    unsigned u = __float_as_uint(v); return ((ull)u << 32) | (ull)u;
}
__device__ __forceinline__ float f32x2_lo(ull a) { return __uint_as_float((unsigned)a); }
__device__ __forceinline__ float f32x2_hi(ull a) { return __uint_as_float((unsigned)(a >> 32)); }

// ---------------------------------------------------------------------------
// Kernel 1: f_input = features @ FC. Tile 32(M)x64(N), 256 threads, f32x2.
// grid (CV/64=4, NV/32=24) = 96 blocks.
// ---------------------------------------------------------------------------
__global__ void k_fin(const float* __restrict__ feat, const float* __restrict__ FCm) {
    __shared__ ull   sa2[32 * 32];   // A (features), value-duplicated pairs
    __shared__ float sb[32 * 64];    // B (FC) rows

    const int tid = threadIdx.x;
    const int tx = tid & 15;         // j-pair group
    const int ty = tid >> 4;         // i group
    const int i0 = blockIdx.y * 32;
    const int j0 = blockIdx.x * 64;

    ull acc[2][2] = {{0ull, 0ull}, {0ull, 0ull}};

    for (int k0 = 0; k0 < CV; k0 += 32) {
        #pragma unroll
        for (int l = 0; l < 4; l++) {
            int idx = tid + l * 256;         // 0..1023
            int r = idx >> 5, kc = idx & 31;
            sa2[idx] = f32x2_dup(feat[(i0 + r) * CV + k0 + kc]);
        }
        #pragma unroll
        for (int l = 0; l < 2; l++) {
            int i4 = tid + l * 256;          // 0..511 float4s
            int kc = i4 >> 4, j4 = i4 & 15;
            *(float4*)&sb[kc * 64 + j4 * 4] =
                *(const float4*)&FCm[(k0 + kc) * CV + j0 + j4 * 4];
        }
        __syncthreads();

        #pragma unroll 8
        for (int kc = 0; kc < 32; kc++) {
            ull a0 = sa2[ty * 32 + kc];
            ull a1 = sa2[(ty + 16) * 32 + kc];
            ull b0 = *(const ull*)&sb[kc * 64 + 2 * tx];
            ull b1 = *(const ull*)&sb[kc * 64 + 2 * tx + 32];
            acc[0][0] = f32x2_fma(a0, b0, acc[0][0]);
            acc[0][1] = f32x2_fma(a0, b1, acc[0][1]);
            acc[1][0] = f32x2_fma(a1, b0, acc[1][0]);
            acc[1][1] = f32x2_fma(a1, b1, acc[1][1]);
        }
        __syncthreads();
    }

    #pragma unroll
    for (int kk = 0; kk < 2; kk++) {
        int i = i0 + ty + 16 * kk;
        #pragma unroll
        for (int m = 0; m < 2; m++) {
            int j = j0 + 2 * tx + 32 * m;
            *(ull*)&g_fin[i * CV + j] = acc[kk][m];   // 8B-aligned pair store
        }
    }
}

// ---------------------------------------------------------------------------
// Kernel 2: per-row prep. u, v, P, Q, lwp. One block per row.
// ---------------------------------------------------------------------------
__global__ void k_prep(const float* __restrict__ coord,
                       const float* __restrict__ fc_w, const float* __restrict__ fc_b,
                       const float* __restrict__ sc_w, const float* __restrict__ sc_b,
                       const float* __restrict__ lin_w) {
    const int i = blockIdx.x;
    const int t = threadIdx.x;   // 256
    const float w0 = fc_w[0], w1 = fc_w[1], bf = fc_b[0];

    float f = g_fin[i * CV + t];
    float u = w0 * f;
    float v = fmaf(w1, f, bf);
    g_u[i * KP + t] = u;
    g_v[i * KP + t] = v;

    float lw = lin_w[t];
    float pu = lw * u;
    float pv = lw * v;

    if (t < KP - CV) {                // t < 16 handles channels 256..271
        int c2 = CV + t;
        float uu = 0.f, vv = 0.f, lw2 = 0.f;
        if (c2 < CV + 3) {
            float cd = coord[i * 3 + t];
            uu  = sc_w[0] * cd;
            vv  = fmaf(sc_w[1], cd, sc_b[0]);
            lw2 = lin_w[c2];
        }
        g_u[i * KP + c2] = uu;
        g_v[i * KP + c2] = vv;
        pu = fmaf(lw2, uu, pu);
        pv = fmaf(lw2, vv, pv);
    }

    if (i == 0) {
        g_lwp[t] = 0.4f * lin_w[t];
        if (t < KP - CV) {
            int c2 = CV + t;
            g_lwp[c2] = (c2 < CV + 3) ? 0.4f * lin_w[c2] : 0.f;
        }
    }

    __shared__ float rp[256], rq[256];
    rp[t] = pu; rq[t] = pv;
    __syncthreads();
    #pragma unroll
    for (int s = 128; s > 0; s >>= 1) {
        if (t < s) { rp[t] += rp[t + s]; rq[t] += rq[t + s]; }
        __syncthreads();
    }
    if (t == 0) { g_P[i] = rp[0]; g_Q[i] = rq[0]; }
}

// ---------------------------------------------------------------------------
// Kernel 3: scores. 64x64 tile, 256 threads, 4x4 micro, channel-packed f32x2.
// Entire 64x272 u/v tiles staged once in dynamic smem (141KB, 1 block/SM).
// score(i,j) = leaky( 0.6*(P_i+Q_j) + lin_b + sum_c lwp[c]*|u_i[c]+v_j[c]| )
// ---------------------------------------------------------------------------
#define SROW 274   // 272 + pad(2): 274%32=18 -> 16 distinct even bank residues
#define SMEM_SCORES ((2 * 64 * SROW + KP + 8) * 4)

__global__ void __launch_bounds__(256, 1) k_scores(const float* __restrict__ lin_b) {
    extern __shared__ float smem[];
    float* su  = smem;                  // [64][SROW]
    float* sv  = smem + 64 * SROW;      // [64][SROW]
    float* slw = smem + 2 * 64 * SROW;  // [KP]

    const int tid = threadIdx.x;
    const int tx = tid & 15;
    const int ty = tid >> 4;
    const int i0 = blockIdx.y * 64;
    const int j0 = blockIdx.x * 64;

    // Fill: each thread copies 17 float4 of one u row and one v row.
    {
        const int r = tid >> 2, l4 = tid & 3;
        const float4* gu = (const float4*)&g_u[(i0 + r) * KP];
        const float4* gv = (const float4*)&g_v[(j0 + r) * KP];
        float* sur = &su[r * SROW];
        float* svr = &sv[r * SROW];
        #pragma unroll
        for (int q = 0; q < 17; q++) {
            float4 a = gu[l4 + q * 4];
            float4 b = gv[l4 + q * 4];
            int o = (l4 + q * 4) * 4;
            *(float2*)&sur[o]     = make_float2(a.x, a.y);
            *(float2*)&sur[o + 2] = make_float2(a.z, a.w);
            *(float2*)&svr[o]     = make_float2(b.x, b.y);
            *(float2*)&svr[o + 2] = make_float2(b.z, b.w);
        }
        slw[tid] = g_lwp[tid];                    // 0..255
        if (tid < KP - 256) slw[256 + tid] = g_lwp[256 + tid];   // 256..271 (was the R2 bug)
    }
    __syncthreads();

    const float* sup[4];
    const float* svp[4];
    #pragma unroll
    for (int k = 0; k < 4; k++) sup[k] = &su[(ty + 16 * k) * SROW];
    #pragma unroll
    for (int m = 0; m < 4; m++) svp[m] = &sv[(tx + 16 * m) * SROW];

    ull acc[4][4];
    #pragma unroll
    for (int k = 0; k < 4; k++)
        #pragma unroll
        for (int m = 0; m < 4; m++) acc[k][m] = 0ull;

    #pragma unroll 4
    for (int cc = 0; cc < KP; cc += 2) {
        ull w2 = *(const ull*)&slw[cc];
        ull a_[4], b_[4];
        #pragma unroll
        for (int k = 0; k < 4; k++) a_[k] = *(const ull*)&sup[k][cc];
        #pragma unroll
        for (int m = 0; m < 4; m++) b_[m] = *(const ull*)&svp[m][cc];
        #pragma unroll
        for (int k = 0; k < 4; k++)
            #pragma unroll
            for (int m = 0; m < 4; m++) {
                ull t = f32x2_abs(f32x2_add(a_[k], b_[m]));
                acc[k][m] = f32x2_fma(w2, t, acc[k][m]);
            }
    }

    const float lb = lin_b[0];
    float Pi[4], Qj[4];
    #pragma unroll
    for (int k = 0; k < 4; k++) Pi[k] = g_P[i0 + ty + 16 * k];
    #pragma unroll
    for (int m = 0; m < 4; m++) Qj[m] = g_Q[j0 + tx + 16 * m];

    #pragma unroll
    for (int k = 0; k < 4; k++) {
        int i = i0 + ty + 16 * k;
        #pragma unroll
        for (int m = 0; m < 4; m++) {
            int j = j0 + tx + 16 * m;
            float s = fmaf(0.6f, Pi[k] + Qj[m], lb)
                      + f32x2_lo(acc[k][m]) + f32x2_hi(acc[k][m]);
            g_att[i * NV + j] = fmaxf(s, 0.2f * s);   // leaky(0.2)
        }
    }
}

// ---------------------------------------------------------------------------
// Kernel 4: row softmax, warp-per-row. grid 96, block 256 (8 warps).
// ---------------------------------------------------------------------------
__global__ void k_softmax() {
    const int w = threadIdx.x >> 5, lane = threadIdx.x & 31;
    const int row = blockIdx.x * 8 + w;
    float4* p = (float4*)&g_att[row * NV];   // 192 float4 per row

    float4 x[6];
    #pragma unroll
    for (int l = 0; l < 6; l++) x[l] = p[lane + 32 * l];

    float m = -1e30f;
    #pragma unroll
    for (int l = 0; l < 6; l++) {
        m = fmaxf(m, fmaxf(fmaxf(x[l].x, x[l].y), fmaxf(x[l].z, x[l].w)));
    }
    #pragma unroll
    for (int s = 16; s > 0; s >>= 1) m = fmaxf(m, __shfl_xor_sync(0xffffffffu, m, s));

    float sum = 0.f;
    #pragma unroll
    for (int l = 0; l < 6; l++) {
        x[l].x = __expf(x[l].x - m); x[l].y = __expf(x[l].y - m);
        x[l].z = __expf(x[l].z - m); x[l].w = __expf(x[l].w - m);
        sum += (x[l].x + x[l].y) + (x[l].z + x[l].w);
    }
    #pragma unroll
    for (int s = 16; s > 0; s >>= 1) sum += __shfl_xor_sync(0xffffffffu, sum, s);
    float inv = 1.0f / sum;

    #pragma unroll
    for (int l = 0; l < 6; l++) {
        x[l].x *= inv; x[l].y *= inv; x[l].z *= inv; x[l].w *= inv;
        p[lane + 32 * l] = x[l];
    }
}

// ---------------------------------------------------------------------------
// Kernel 5: out = elu(attention @ f_input). Tile 32x64, 256 threads, f32x2.
// grid (CV/64=4, NV/32=24) = 96 blocks, K = 768 in stages of 32.
// ---------------------------------------------------------------------------
__global__ void k_out(float* __restrict__ out) {
    __shared__ ull   sa2[32 * 32];   // attention, value-duplicated pairs
    __shared__ float sb[32 * 64];    // f_input rows

    const int tid = threadIdx.x;
    const int tx = tid & 15;
    const int ty = tid >> 4;
    const int i0 = blockIdx.y * 32;
    const int j0 = blockIdx.x * 64;

    ull acc[2][2] = {{0ull, 0ull}, {0ull, 0ull}};

    for (int k0 = 0; k0 < NV; k0 += 32) {
        #pragma unroll
        for (int l = 0; l < 4; l++) {
            int idx = tid + l * 256;
            int r = idx >> 5, kc = idx & 31;
            sa2[idx] = f32x2_dup(g_att[(i0 + r) * NV + k0 + kc]);
        }
        #pragma unroll
        for (int l = 0; l < 2; l++) {
            int i4 = tid + l * 256;
            int kc = i4 >> 4, j4 = i4 & 15;
            *(float4*)&sb[kc * 64 + j4 * 4] =
                *(const float4*)&g_fin[(k0 + kc) * CV + j0 + j4 * 4];
        }
        __syncthreads();

        #pragma unroll 8
        for (int kc = 0; kc < 32; kc++) {
            ull a0 = sa2[ty * 32 + kc];
            ull a1 = sa2[(ty + 16) * 32 + kc];
            ull b0 = *(const ull*)&sb[kc * 64 + 2 * tx];
            ull b1 = *(const ull*)&sb[kc * 64 + 2 * tx + 32];
            acc[0][0] = f32x2_fma(a0, b0, acc[0][0]);
            acc[0][1] = f32x2_fma(a0, b1, acc[0][1]);
            acc[1][0] = f32x2_fma(a1, b0, acc[1][0]);
            acc[1][1] = f32x2_fma(a1, b1, acc[1][1]);
        }
        __syncthreads();
    }

    #pragma unroll
    for (int kk = 0; kk < 2; kk++) {
        int i = i0 + ty + 16 * kk;
        #pragma unroll
        for (int m = 0; m < 2; m++) {
            int j = j0 + 2 * tx + 32 * m;
            float h0 = f32x2_lo(acc[kk][m]);
            float h1 = f32x2_hi(acc[kk][m]);
            float2 r;
            r.x = (h0 > 0.f) ? h0 : (__expf(h0) - 1.0f);
            r.y = (h1 > 0.f) ? h1 : (__expf(h1) - 1.0f);
            *(float2*)&out[i * CV + j] = r;
        }
    }
}

// ---------------------------------------------------------------------------
extern "C" void kernel_launch(void* const* d_in, const int* in_sizes, int n_in,
                              void* d_out, int out_size) {
    const float* feat  = (const float*)d_in[0];
    const float* coord = (const float*)d_in[1];
    // d_in[2] = adj (unused by forward)
    const float* FCm   = (const float*)d_in[3];
    const float* fc_w  = (const float*)d_in[4];
    const float* fc_b  = (const float*)d_in[5];
    const float* sc_w  = (const float*)d_in[6];
    const float* sc_b  = (const float*)d_in[7];
    const float* lin_w = (const float*)d_in[8];
    const float* lin_b = (const float*)d_in[9];
    float* out = (float*)d_out;

    cudaFuncSetAttribute(k_scores, cudaFuncAttributeMaxDynamicSharedMemorySize,
                         SMEM_SCORES);

    dim3 gf(CV / 64, NV / 32);
    k_fin<<<gf, 256>>>(feat, FCm);
    k_prep<<<NV, 256>>>(coord, fc_w, fc_b, sc_w, sc_b, lin_w);
    dim3 gs(NV / 64, NV / 64);
    k_scores<<<gs, 256, SMEM_SCORES>>>(lin_b);
    k_softmax<<<NV / 8, 256>>>();
    dim3 go(CV / 64, NV / 32);
    k_out<<<go, 256>>>(out);
}

// round 4
// speedup vs baseline: 1.4090x; 1.0285x over previous
#include <cuda_runtime.h>

#define NV 768
#define CV 256

typedef unsigned long long ull;

// Scratch (device globals: allocation-free)
__device__ float g_fin[NV * CV];        // f_input
__device__ float g_Spart[4 * NV];       // per-jblock partial S_i = sum_c lw[c]*f[i][c]
__device__ float g_Lw;                  // sum of lin_w[0..255]
__device__ float g_att[NV * NV];        // scores, then attention (in place)

// ---------------- packed f32x2 helpers (sm_103a) ----------------
__device__ __forceinline__ ull f32x2_add(ull a, ull b) {
    ull r; asm("add.rn.f32x2 %0, %1, %2;" : "=l"(r) : "l"(a), "l"(b)); return r;
}
__device__ __forceinline__ ull f32x2_fma(ull a, ull b, ull c) {
    ull r; asm("fma.rn.f32x2 %0, %1, %2, %3;" : "=l"(r) : "l"(a), "l"(b), "l"(c)); return r;
}
__device__ __forceinline__ ull f32x2_abs(ull a) { return a & 0x7FFFFFFF7FFFFFFFULL; }
__device__ __forceinline__ ull f32x2_dup(float v) {
    unsigned u = __float_as_uint(v); return ((ull)u << 32) | (ull)u;
}
__device__ __forceinline__ float f32x2_lo(ull a) { return __uint_as_float((unsigned)a); }
__device__ __forceinline__ float f32x2_hi(ull a) { return __uint_as_float((unsigned)(a >> 32)); }

// ---------------------------------------------------------------------------
// Kernel 1: f_input = features @ FC (+ S partials, + Lw). Tile 32x64, 256 thr.
// grid (CV/64=4, NV/32=24) = 96 blocks.
// ---------------------------------------------------------------------------
__global__ void k_fin(const float* __restrict__ feat, const float* __restrict__ FCm,
                      const float* __restrict__ lin_w) {
    __shared__ ull   sa2[32 * 32];   // A (features), value-duplicated pairs
    __shared__ float sb[32 * 64];    // B (FC) rows

    const int tid = threadIdx.x;
    const int tx = tid & 15;         // j-pair group
    const int ty = tid >> 4;         // i group
    const int i0 = blockIdx.y * 32;
    const int j0 = blockIdx.x * 64;

    ull acc[2][2] = {{0ull, 0ull}, {0ull, 0ull}};

    for (int k0 = 0; k0 < CV; k0 += 32) {
        #pragma unroll
        for (int l = 0; l < 4; l++) {
            int idx = tid + l * 256;         // 0..1023
            int r = idx >> 5, kc = idx & 31;
            sa2[idx] = f32x2_dup(feat[(i0 + r) * CV + k0 + kc]);
        }
        #pragma unroll
        for (int l = 0; l < 2; l++) {
            int i4 = tid + l * 256;          // 0..511 float4s
            int kc = i4 >> 4, j4 = i4 & 15;
            *(float4*)&sb[kc * 64 + j4 * 4] =
                *(const float4*)&FCm[(k0 + kc) * CV + j0 + j4 * 4];
        }
        __syncthreads();

        #pragma unroll 8
        for (int kc = 0; kc < 32; kc++) {
            ull a0 = sa2[ty * 32 + kc];
            ull a1 = sa2[(ty + 16) * 32 + kc];
            ull b0 = *(const ull*)&sb[kc * 64 + 2 * tx];
            ull b1 = *(const ull*)&sb[kc * 64 + 2 * tx + 32];
            acc[0][0] = f32x2_fma(a0, b0, acc[0][0]);
            acc[0][1] = f32x2_fma(a0, b1, acc[0][1]);
            acc[1][0] = f32x2_fma(a1, b0, acc[1][0]);
            acc[1][1] = f32x2_fma(a1, b1, acc[1][1]);
        }
        __syncthreads();
    }

    // lin_w for my 4 columns
    const float lw00 = lin_w[j0 + 2 * tx],      lw01 = lin_w[j0 + 2 * tx + 1];
    const float lw10 = lin_w[j0 + 2 * tx + 32], lw11 = lin_w[j0 + 2 * tx + 33];

    #pragma unroll
    for (int kk = 0; kk < 2; kk++) {
        int i = i0 + ty + 16 * kk;
        #pragma unroll
        for (int m = 0; m < 2; m++) {
            int j = j0 + 2 * tx + 32 * m;
            *(ull*)&g_fin[i * CV + j] = acc[kk][m];   // 8B-aligned pair store
        }
        // partial S_i over this block's 64 columns
        float s = f32x2_lo(acc[kk][0]) * lw00 + f32x2_hi(acc[kk][0]) * lw01
                + f32x2_lo(acc[kk][1]) * lw10 + f32x2_hi(acc[kk][1]) * lw11;
        #pragma unroll
        for (int off = 8; off > 0; off >>= 1)
            s += __shfl_down_sync(0xffffffffu, s, off, 16);
        if (tx == 0) g_Spart[blockIdx.x * NV + i] = s;
    }

    // block (0,0): Lw = sum lin_w[0..255]
    if (blockIdx.x == 0 && blockIdx.y == 0) {
        __syncthreads();            // main-loop smem reads are done
        sb[tid] = lin_w[tid];
        __syncthreads();
        #pragma unroll
        for (int s = 128; s > 0; s >>= 1) {
            if (tid < s) sb[tid] += sb[tid + s];
            __syncthreads();
        }
        if (tid == 0) g_Lw = sb[0];
    }
}

// ---------------------------------------------------------------------------
// Kernel 2: scores. 64x64 tile, 256 threads, 4x4 micro, channel-packed f32x2.
// u/v derived from g_fin during fill; coord channels + P/Q analytic epilogue.
// score(i,j) = leaky( 0.6*(P_i+Q_j) + lin_b + sum_c 0.4*lw[c]*|u_i[c]+v_j[c]| )
// ---------------------------------------------------------------------------
#define SROW 258   // 256 + pad(2): tx stride mod 32 = 2 -> conflict-free LDS.64
#define SMEM_SCORES ((2 * 64 * SROW + 256 + 2 * 192 + 16) * 4)

__global__ void __launch_bounds__(256, 1) k_scores(
        const float* __restrict__ coord,
        const float* __restrict__ fc_w, const float* __restrict__ fc_b,
        const float* __restrict__ sc_w, const float* __restrict__ sc_b,
        const float* __restrict__ lin_w, const float* __restrict__ lin_b) {
    extern __shared__ float smem[];
    float* su  = smem;                        // [64][SROW]  u = w0*f_i
    float* sv  = smem + 64 * SROW;            // [64][SROW]  v = w1*f_j + bf
    float* slw = smem + 2 * 64 * SROW;        // [256]       0.4*lin_w
    float* scu = slw + 256;                   // [64*3]      sc_w0*coord_i
    float* scv = scu + 192;                   // [64*3]      sc_w1*coord_j + sc_b

    const int tid = threadIdx.x;
    const int tx = tid & 15;
    const int ty = tid >> 4;
    const int i0 = blockIdx.y * 64;
    const int j0 = blockIdx.x * 64;

    const float w0 = fc_w[0], w1 = fc_w[1], bf = fc_b[0];

    // Fill: each thread copies 16 float4 of one i-row (as u) and one j-row (as v).
    {
        const int r = tid >> 2, l4 = tid & 3;
        const float4* gi = (const float4*)&g_fin[(i0 + r) * CV];
        const float4* gj = (const float4*)&g_fin[(j0 + r) * CV];
        float* sur = &su[r * SROW];
        float* svr = &sv[r * SROW];
        #pragma unroll
        for (int q = 0; q < 16; q++) {
            float4 a = gi[l4 + q * 4];
            float4 b = gj[l4 + q * 4];
            int o = (l4 + q * 4) * 4;
            sur[o]     = w0 * a.x; sur[o + 1] = w0 * a.y;
            sur[o + 2] = w0 * a.z; sur[o + 3] = w0 * a.w;
            svr[o]     = fmaf(w1, b.x, bf); svr[o + 1] = fmaf(w1, b.y, bf);
            svr[o + 2] = fmaf(w1, b.z, bf); svr[o + 3] = fmaf(w1, b.w, bf);
        }
        slw[tid] = 0.4f * lin_w[tid];
        if (tid < 192) {
            int rr = tid / 3, k = tid - rr * 3;
            scu[tid] = sc_w[0] * coord[(i0 + rr) * 3 + k];
            scv[tid] = fmaf(sc_w[1], coord[(j0 + rr) * 3 + k], sc_b[0]);
        }
    }
    __syncthreads();

    const float* sup[4];
    const float* svp[4];
    #pragma unroll
    for (int k = 0; k < 4; k++) sup[k] = &su[(ty + 16 * k) * SROW];
    #pragma unroll
    for (int m = 0; m < 4; m++) svp[m] = &sv[(tx + 16 * m) * SROW];

    ull acc[4][4];
    #pragma unroll
    for (int k = 0; k < 4; k++)
        #pragma unroll
        for (int m = 0; m < 4; m++) acc[k][m] = 0ull;

    #pragma unroll 4
    for (int cc = 0; cc < CV; cc += 2) {
        ull w2 = *(const ull*)&slw[cc];
        ull a_[4], b_[4];
        #pragma unroll
        for (int k = 0; k < 4; k++) a_[k] = *(const ull*)&sup[k][cc];
        #pragma unroll
        for (int m = 0; m < 4; m++) b_[m] = *(const ull*)&svp[m][cc];
        #pragma unroll
        for (int k = 0; k < 4; k++)
            #pragma unroll
            for (int m = 0; m < 4; m++) {
                ull t = f32x2_abs(f32x2_add(a_[k], b_[m]));
                acc[k][m] = f32x2_fma(w2, t, acc[k][m]);
            }
    }

    // Epilogue scalars
    const float lb  = lin_b[0];
    const float Lw  = g_Lw;
    const float lc0 = lin_w[CV], lc1 = lin_w[CV + 1], lc2 = lin_w[CV + 2];
    const float base0 = fmaf(0.6f * bf, Lw, lb);

    float Si[4], Sj[4];
    #pragma unroll
    for (int k = 0; k < 4; k++) {
        int i = i0 + ty + 16 * k;
        Si[k] = g_Spart[i] + g_Spart[NV + i] + g_Spart[2 * NV + i] + g_Spart[3 * NV + i];
    }
    #pragma unroll
    for (int m = 0; m < 4; m++) {
        int j = j0 + tx + 16 * m;
        Sj[m] = g_Spart[j] + g_Spart[NV + j] + g_Spart[2 * NV + j] + g_Spart[3 * NV + j];
    }

    #pragma unroll
    for (int k = 0; k < 4; k++) {
        int ir = ty + 16 * k;
        float cu0 = scu[ir * 3], cu1 = scu[ir * 3 + 1], cu2 = scu[ir * 3 + 2];
        #pragma unroll
        for (int m = 0; m < 4; m++) {
            int jr = tx + 16 * m;
            // coordinate channels: lc * leaky_decomp(t) = lc*(0.6t + 0.4|t|)
            float t0 = cu0 + scv[jr * 3];
            float t1 = cu1 + scv[jr * 3 + 1];
            float t2 = cu2 + scv[jr * 3 + 2];
            float ct = lc0 * fmaf(0.4f, fabsf(t0), 0.6f * t0)
                     + lc1 * fmaf(0.4f, fabsf(t1), 0.6f * t1)
                     + lc2 * fmaf(0.4f, fabsf(t2), 0.6f * t2);
            float s = fmaf(0.6f, fmaf(w0, Si[k], w1 * Sj[m]), base0) + ct
                      + f32x2_lo(acc[k][m]) + f32x2_hi(acc[k][m]);
            g_att[(i0 + ir) * NV + (j0 + jr)] = fmaxf(s, 0.2f * s);   // leaky(0.2)
        }
    }
}

// ---------------------------------------------------------------------------
// Kernel 3: row softmax. grid 384, block 64 (2 warps, warp-per-row).
// ---------------------------------------------------------------------------
__global__ void k_softmax() {
    const int w = threadIdx.x >> 5, lane = threadIdx.x & 31;
    const int row = blockIdx.x * 2 + w;
    float4* p = (float4*)&g_att[row * NV];   // 192 float4 per row

    float4 x[6];
    #pragma unroll
    for (int l = 0; l < 6; l++) x[l] = p[lane + 32 * l];

    float m = -1e30f;
    #pragma unroll
    for (int l = 0; l < 6; l++)
        m = fmaxf(m, fmaxf(fmaxf(x[l].x, x[l].y), fmaxf(x[l].z, x[l].w)));
    #pragma unroll
    for (int s = 16; s > 0; s >>= 1) m = fmaxf(m, __shfl_xor_sync(0xffffffffu, m, s));

    float sum = 0.f;
    #pragma unroll
    for (int l = 0; l < 6; l++) {
        x[l].x = __expf(x[l].x - m); x[l].y = __expf(x[l].y - m);
        x[l].z = __expf(x[l].z - m); x[l].w = __expf(x[l].w - m);
        sum += (x[l].x + x[l].y) + (x[l].z + x[l].w);
    }
    #pragma unroll
    for (int s = 16; s > 0; s >>= 1) sum += __shfl_xor_sync(0xffffffffu, sum, s);
    float inv = 1.0f / sum;

    #pragma unroll
    for (int l = 0; l < 6; l++) {
        x[l].x *= inv; x[l].y *= inv; x[l].z *= inv; x[l].w *= inv;
        p[lane + 32 * l] = x[l];
    }
}

// ---------------------------------------------------------------------------
// Kernel 4: out = elu(attention @ f_input). Tile 32x64, 256 threads, f32x2.
// ---------------------------------------------------------------------------
__global__ void k_out(float* __restrict__ out) {
    __shared__ ull   sa2[32 * 32];   // attention, value-duplicated pairs
    __shared__ float sb[32 * 64];    // f_input rows

    const int tid = threadIdx.x;
    const int tx = tid & 15;
    const int ty = tid >> 4;
    const int i0 = blockIdx.y * 32;
    const int j0 = blockIdx.x * 64;

    ull acc[2][2] = {{0ull, 0ull}, {0ull, 0ull}};

    for (int k0 = 0; k0 < NV; k0 += 32) {
        #pragma unroll
        for (int l = 0; l < 4; l++) {
            int idx = tid + l * 256;
            int r = idx >> 5, kc = idx & 31;
            sa2[idx] = f32x2_dup(g_att[(i0 + r) * NV + k0 + kc]);
        }
        #pragma unroll
        for (int l = 0; l < 2; l++) {
            int i4 = tid + l * 256;
            int kc = i4 >> 4, j4 = i4 & 15;
            *(float4*)&sb[kc * 64 + j4 * 4] =
                *(const float4*)&g_fin[(k0 + kc) * CV + j0 + j4 * 4];
        }
        __syncthreads();

        #pragma unroll 8
        for (int kc = 0; kc < 32; kc++) {
            ull a0 = sa2[ty * 32 + kc];
            ull a1 = sa2[(ty + 16) * 32 + kc];
            ull b0 = *(const ull*)&sb[kc * 64 + 2 * tx];
            ull b1 = *(const ull*)&sb[kc * 64 + 2 * tx + 32];
            acc[0][0] = f32x2_fma(a0, b0, acc[0][0]);
            acc[0][1] = f32x2_fma(a0, b1, acc[0][1]);
            acc[1][0] = f32x2_fma(a1, b0, acc[1][0]);
            acc[1][1] = f32x2_fma(a1, b1, acc[1][1]);
        }
        __syncthreads();
    }

    #pragma unroll
    for (int kk = 0; kk < 2; kk++) {
        int i = i0 + ty + 16 * kk;
        #pragma unroll
        for (int m = 0; m < 2; m++) {
            int j = j0 + 2 * tx + 32 * m;
            float h0 = f32x2_lo(acc[kk][m]);
            float h1 = f32x2_hi(acc[kk][m]);
            float2 r;
            r.x = (h0 > 0.f) ? h0 : (__expf(h0) - 1.0f);
            r.y = (h1 > 0.f) ? h1 : (__expf(h1) - 1.0f);
            *(float2*)&out[i * CV + j] = r;
        }
    }
}

// ---------------------------------------------------------------------------
extern "C" void kernel_launch(void* const* d_in, const int* in_sizes, int n_in,
                              void* d_out, int out_size) {
    const float* feat  = (const float*)d_in[0];
    const float* coord = (const float*)d_in[1];
    // d_in[2] = adj (unused by forward)
    const float* FCm   = (const float*)d_in[3];
    const float* fc_w  = (const float*)d_in[4];
    const float* fc_b  = (const float*)d_in[5];
    const float* sc_w  = (const float*)d_in[6];
    const float* sc_b  = (const float*)d_in[7];
    const float* lin_w = (const float*)d_in[8];
    const float* lin_b = (const float*)d_in[9];
    float* out = (float*)d_out;

    cudaFuncSetAttribute(k_scores, cudaFuncAttributeMaxDynamicSharedMemorySize,
                         SMEM_SCORES);

    dim3 gf(CV / 64, NV / 32);
    k_fin<<<gf, 256>>>(feat, FCm, lin_w);
    dim3 gs(NV / 64, NV / 64);
    k_scores<<<gs, 256, SMEM_SCORES>>>(coord, fc_w, fc_b, sc_w, sc_b, lin_w, lin_b);
    k_softmax<<<NV / 2, 64>>>();
    dim3 go(CV / 64, NV / 32);
    k_out<<<go, 256>>>(out);
}

// round 5
// speedup vs baseline: 1.4580x; 1.0348x over previous
#include <cuda_runtime.h>

#define NV 768
#define CV 256

typedef unsigned long long ull;

// Scratch (device globals: allocation-free)
__device__ float g_fin[NV * CV];        // f_input
__device__ float g_Spart[4 * NV];       // per-jblock partial S_i = sum_c lw[c]*f[i][c]
__device__ float g_Lw;                  // sum of lin_w[0..255]
__device__ float g_att[NV * NV];        // scores, then attention (in place)

// ---------------- packed f32x2 helpers (sm_103a) ----------------
__device__ __forceinline__ ull f32x2_add(ull a, ull b) {
    ull r; asm("add.rn.f32x2 %0, %1, %2;" : "=l"(r) : "l"(a), "l"(b)); return r;
}
__device__ __forceinline__ ull f32x2_fma(ull a, ull b, ull c) {
    ull r; asm("fma.rn.f32x2 %0, %1, %2, %3;" : "=l"(r) : "l"(a), "l"(b), "l"(c)); return r;
}
__device__ __forceinline__ ull f32x2_abs(ull a) { return a & 0x7FFFFFFF7FFFFFFFULL; }
__device__ __forceinline__ ull f32x2_dup(float v) {
    unsigned u = __float_as_uint(v); return ((ull)u << 32) | (ull)u;
}
__device__ __forceinline__ float f32x2_lo(ull a) { return __uint_as_float((unsigned)a); }
__device__ __forceinline__ float f32x2_hi(ull a) { return __uint_as_float((unsigned)(a >> 32)); }

// ---------------------------------------------------------------------------
// Kernel 1: f_input = features @ FC (+ S partials, + Lw).
// Tile 16(M)x64(N), 128 threads, grid (CV/64=4, NV/16=48) = 192 blocks.
// ---------------------------------------------------------------------------
__global__ void k_fin(const float* __restrict__ feat, const float* __restrict__ FCm,
                      const float* __restrict__ lin_w) {
    __shared__ ull   sa2[16 * 32];   // A (features), value-duplicated pairs, 4KB
    __shared__ float sb[32 * 64];    // B (FC) rows, 8KB

    const int tid = threadIdx.x;     // 128
    const int tx = tid & 15;         // j-pair group
    const int ty = tid >> 4;         // 0..7, i group
    const int i0 = blockIdx.y * 16;
    const int j0 = blockIdx.x * 64;

    ull acc[2][2] = {{0ull, 0ull}, {0ull, 0ull}};

    for (int k0 = 0; k0 < CV; k0 += 32) {
        #pragma unroll
        for (int l = 0; l < 4; l++) {
            int idx = tid + l * 128;         // 0..511
            int r = idx >> 5, kc = idx & 31;
            sa2[idx] = f32x2_dup(feat[(i0 + r) * CV + k0 + kc]);
        }
        #pragma unroll
        for (int l = 0; l < 4; l++) {
            int i4 = tid + l * 128;          // 0..511 float4s
            int kc = i4 >> 4, j4 = i4 & 15;
            *(float4*)&sb[kc * 64 + j4 * 4] =
                *(const float4*)&FCm[(k0 + kc) * CV + j0 + j4 * 4];
        }
        __syncthreads();

        #pragma unroll 8
        for (int kc = 0; kc < 32; kc++) {
            ull a0 = sa2[ty * 32 + kc];
            ull a1 = sa2[(ty + 8) * 32 + kc];
            ull b0 = *(const ull*)&sb[kc * 64 + 2 * tx];
            ull b1 = *(const ull*)&sb[kc * 64 + 2 * tx + 32];
            acc[0][0] = f32x2_fma(a0, b0, acc[0][0]);
            acc[0][1] = f32x2_fma(a0, b1, acc[0][1]);
            acc[1][0] = f32x2_fma(a1, b0, acc[1][0]);
            acc[1][1] = f32x2_fma(a1, b1, acc[1][1]);
        }
        __syncthreads();
    }

    // lin_w for my 4 columns
    const float lw00 = lin_w[j0 + 2 * tx],      lw01 = lin_w[j0 + 2 * tx + 1];
    const float lw10 = lin_w[j0 + 2 * tx + 32], lw11 = lin_w[j0 + 2 * tx + 33];

    #pragma unroll
    for (int kk = 0; kk < 2; kk++) {
        int i = i0 + ty + 8 * kk;
        #pragma unroll
        for (int m = 0; m < 2; m++) {
            int j = j0 + 2 * tx + 32 * m;
            *(ull*)&g_fin[i * CV + j] = acc[kk][m];   // 8B-aligned pair store
        }
        // partial S_i over this block's 64 columns
        float s = f32x2_lo(acc[kk][0]) * lw00 + f32x2_hi(acc[kk][0]) * lw01
                + f32x2_lo(acc[kk][1]) * lw10 + f32x2_hi(acc[kk][1]) * lw11;
        #pragma unroll
        for (int off = 8; off > 0; off >>= 1)
            s += __shfl_down_sync(0xffffffffu, s, off, 16);
        if (tx == 0) g_Spart[blockIdx.x * NV + i] = s;
    }

    // block (0,0): Lw = sum lin_w[0..255]
    if (blockIdx.x == 0 && blockIdx.y == 0) {
        __syncthreads();            // main-loop smem reads are done
        sb[tid] = lin_w[tid] + lin_w[tid + 128];
        __syncthreads();
        #pragma unroll
        for (int s = 64; s > 0; s >>= 1) {
            if (tid < s) sb[tid] += sb[tid + s];
            __syncthreads();
        }
        if (tid == 0) g_Lw = sb[0];
    }
}

// ---------------------------------------------------------------------------
// Kernel 2: scores. 64x64 tile, 256 threads, 4x4 micro, channel-packed f32x2.
// u/v derived from g_fin during fill; coord channels + P/Q analytic epilogue.
// score(i,j) = leaky( 0.6*(P_i+Q_j) + lin_b + sum_c 0.4*lw[c]*|u_i[c]+v_j[c]| )
// ---------------------------------------------------------------------------
#define SROW 258   // 256 + pad(2): tx stride mod 32 = 2 -> conflict-free LDS.64
#define SMEM_SCORES ((2 * 64 * SROW + 256 + 2 * 192 + 16) * 4)

__global__ void __launch_bounds__(256, 1) k_scores(
        const float* __restrict__ coord,
        const float* __restrict__ fc_w, const float* __restrict__ fc_b,
        const float* __restrict__ sc_w, const float* __restrict__ sc_b,
        const float* __restrict__ lin_w, const float* __restrict__ lin_b) {
    extern __shared__ float smem[];
    float* su  = smem;                        // [64][SROW]  u = w0*f_i
    float* sv  = smem + 64 * SROW;            // [64][SROW]  v = w1*f_j + bf
    float* slw = smem + 2 * 64 * SROW;        // [256]       0.4*lin_w
    float* scu = slw + 256;                   // [64*3]      sc_w0*coord_i
    float* scv = scu + 192;                   // [64*3]      sc_w1*coord_j + sc_b

    const int tid = threadIdx.x;
    const int tx = tid & 15;
    const int ty = tid >> 4;
    const int i0 = blockIdx.y * 64;
    const int j0 = blockIdx.x * 64;

    const float w0 = fc_w[0], w1 = fc_w[1], bf = fc_b[0];

    // Fill: each thread copies 16 float4 of one i-row (as u) and one j-row (as v).
    {
        const int r = tid >> 2, l4 = tid & 3;
        const float4* gi = (const float4*)&g_fin[(i0 + r) * CV];
        const float4* gj = (const float4*)&g_fin[(j0 + r) * CV];
        float* sur = &su[r * SROW];
        float* svr = &sv[r * SROW];
        #pragma unroll
        for (int q = 0; q < 16; q++) {
            float4 a = gi[l4 + q * 4];
            float4 b = gj[l4 + q * 4];
            int o = (l4 + q * 4) * 4;
            sur[o]     = w0 * a.x; sur[o + 1] = w0 * a.y;
            sur[o + 2] = w0 * a.z; sur[o + 3] = w0 * a.w;
            svr[o]     = fmaf(w1, b.x, bf); svr[o + 1] = fmaf(w1, b.y, bf);
            svr[o + 2] = fmaf(w1, b.z, bf); svr[o + 3] = fmaf(w1, b.w, bf);
        }
        slw[tid] = 0.4f * lin_w[tid];
        if (tid < 192) {
            int rr = tid / 3, k = tid - rr * 3;
            scu[tid] = sc_w[0] * coord[(i0 + rr) * 3 + k];
            scv[tid] = fmaf(sc_w[1], coord[(j0 + rr) * 3 + k], sc_b[0]);
        }
    }
    __syncthreads();

    const float* sup[4];
    const float* svp[4];
    #pragma unroll
    for (int k = 0; k < 4; k++) sup[k] = &su[(ty + 16 * k) * SROW];
    #pragma unroll
    for (int m = 0; m < 4; m++) svp[m] = &sv[(tx + 16 * m) * SROW];

    ull acc[4][4];
    #pragma unroll
    for (int k = 0; k < 4; k++)
        #pragma unroll
        for (int m = 0; m < 4; m++) acc[k][m] = 0ull;

    #pragma unroll 4
    for (int cc = 0; cc < CV; cc += 2) {
        ull w2 = *(const ull*)&slw[cc];
        ull a_[4], b_[4];
        #pragma unroll
        for (int k = 0; k < 4; k++) a_[k] = *(const ull*)&sup[k][cc];
        #pragma unroll
        for (int m = 0; m < 4; m++) b_[m] = *(const ull*)&svp[m][cc];
        #pragma unroll
        for (int k = 0; k < 4; k++)
            #pragma unroll
            for (int m = 0; m < 4; m++) {
                ull t = f32x2_abs(f32x2_add(a_[k], b_[m]));
                acc[k][m] = f32x2_fma(w2, t, acc[k][m]);
            }
    }

    // Epilogue scalars
    const float lb  = lin_b[0];
    const float Lw  = g_Lw;
    const float lc0 = lin_w[CV], lc1 = lin_w[CV + 1], lc2 = lin_w[CV + 2];
    const float base0 = fmaf(0.6f * bf, Lw, lb);

    float Si[4], Sj[4];
    #pragma unroll
    for (int k = 0; k < 4; k++) {
        int i = i0 + ty + 16 * k;
        Si[k] = g_Spart[i] + g_Spart[NV + i] + g_Spart[2 * NV + i] + g_Spart[3 * NV + i];
    }
    #pragma unroll
    for (int m = 0; m < 4; m++) {
        int j = j0 + tx + 16 * m;
        Sj[m] = g_Spart[j] + g_Spart[NV + j] + g_Spart[2 * NV + j] + g_Spart[3 * NV + j];
    }

    #pragma unroll
    for (int k = 0; k < 4; k++) {
        int ir = ty + 16 * k;
        float cu0 = scu[ir * 3], cu1 = scu[ir * 3 + 1], cu2 = scu[ir * 3 + 2];
        #pragma unroll
        for (int m = 0; m < 4; m++) {
            int jr = tx + 16 * m;
            // coordinate channels: lc * leaky_decomp(t) = lc*(0.6t + 0.4|t|)
            float t0 = cu0 + scv[jr * 3];
            float t1 = cu1 + scv[jr * 3 + 1];
            float t2 = cu2 + scv[jr * 3 + 2];
            float ct = lc0 * fmaf(0.4f, fabsf(t0), 0.6f * t0)
                     + lc1 * fmaf(0.4f, fabsf(t1), 0.6f * t1)
                     + lc2 * fmaf(0.4f, fabsf(t2), 0.6f * t2);
            float s = fmaf(0.6f, fmaf(w0, Si[k], w1 * Sj[m]), base0) + ct
                      + f32x2_lo(acc[k][m]) + f32x2_hi(acc[k][m]);
            g_att[(i0 + ir) * NV + (j0 + jr)] = fmaxf(s, 0.2f * s);   // leaky(0.2)
        }
    }
}

// ---------------------------------------------------------------------------
// Kernel 3: row softmax. grid 384, block 64 (2 warps, warp-per-row).
// ---------------------------------------------------------------------------
__global__ void k_softmax() {
    const int w = threadIdx.x >> 5, lane = threadIdx.x & 31;
    const int row = blockIdx.x * 2 + w;
    float4* p = (float4*)&g_att[row * NV];   // 192 float4 per row

    float4 x[6];
    #pragma unroll
    for (int l = 0; l < 6; l++) x[l] = p[lane + 32 * l];

    float m = -1e30f;
    #pragma unroll
    for (int l = 0; l < 6; l++)
        m = fmaxf(m, fmaxf(fmaxf(x[l].x, x[l].y), fmaxf(x[l].z, x[l].w)));
    #pragma unroll
    for (int s = 16; s > 0; s >>= 1) m = fmaxf(m, __shfl_xor_sync(0xffffffffu, m, s));

    float sum = 0.f;
    #pragma unroll
    for (int l = 0; l < 6; l++) {
        x[l].x = __expf(x[l].x - m); x[l].y = __expf(x[l].y - m);
        x[l].z = __expf(x[l].z - m); x[l].w = __expf(x[l].w - m);
        sum += (x[l].x + x[l].y) + (x[l].z + x[l].w);
    }
    #pragma unroll
    for (int s = 16; s > 0; s >>= 1) sum += __shfl_xor_sync(0xffffffffu, sum, s);
    float inv = 1.0f / sum;

    #pragma unroll
    for (int l = 0; l < 6; l++) {
        x[l].x *= inv; x[l].y *= inv; x[l].z *= inv; x[l].w *= inv;
        p[lane + 32 * l] = x[l];
    }
}

// ---------------------------------------------------------------------------
// Kernel 4: out = elu(attention @ f_input).
// Tile 16(M)x64(N), 128 threads, grid (CV/64=4, NV/16=48) = 192 blocks.
// ---------------------------------------------------------------------------
__global__ void k_out(float* __restrict__ out) {
    __shared__ ull   sa2[16 * 32];   // attention, value-duplicated pairs, 4KB
    __shared__ float sb[32 * 64];    // f_input rows, 8KB

    const int tid = threadIdx.x;     // 128
    const int tx = tid & 15;
    const int ty = tid >> 4;         // 0..7
    const int i0 = blockIdx.y * 16;
    const int j0 = blockIdx.x * 64;

    ull acc[2][2] = {{0ull, 0ull}, {0ull, 0ull}};

    for (int k0 = 0; k0 < NV; k0 += 32) {
        #pragma unroll
        for (int l = 0; l < 4; l++) {
            int idx = tid + l * 128;       // 0..511
            int r = idx >> 5, kc = idx & 31;
            sa2[idx] = f32x2_dup(g_att[(i0 + r) * NV + k0 + kc]);
        }
        #pragma unroll
        for (int l = 0; l < 4; l++) {
            int i4 = tid + l * 128;        // 0..511 float4s
            int kc = i4 >> 4, j4 = i4 & 15;
            *(float4*)&sb[kc * 64 + j4 * 4] =
                *(const float4*)&g_fin[(k0 + kc) * CV + j0 + j4 * 4];
        }
        __syncthreads();

        #pragma unroll 8
        for (int kc = 0; kc < 32; kc++) {
            ull a0 = sa2[ty * 32 + kc];
            ull a1 = sa2[(ty + 8) * 32 + kc];
            ull b0 = *(const ull*)&sb[kc * 64 + 2 * tx];
            ull b1 = *(const ull*)&sb[kc * 64 + 2 * tx + 32];
            acc[0][0] = f32x2_fma(a0, b0, acc[0][0]);
            acc[0][1] = f32x2_fma(a0, b1, acc[0][1]);
            acc[1][0] = f32x2_fma(a1, b0, acc[1][0]);
            acc[1][1] = f32x2_fma(a1, b1, acc[1][1]);
        }
        __syncthreads();
    }

    #pragma unroll
    for (int kk = 0; kk < 2; kk++) {
        int i = i0 + ty + 8 * kk;
        #pragma unroll
        for (int m = 0; m < 2; m++) {
            int j = j0 + 2 * tx + 32 * m;
            float h0 = f32x2_lo(acc[kk][m]);
            float h1 = f32x2_hi(acc[kk][m]);
            float2 r;
            r.x = (h0 > 0.f) ? h0 : (__expf(h0) - 1.0f);
            r.y = (h1 > 0.f) ? h1 : (__expf(h1) - 1.0f);
            *(float2*)&out[i * CV + j] = r;
        }
    }
}

// ---------------------------------------------------------------------------
extern "C" void kernel_launch(void* const* d_in, const int* in_sizes, int n_in,
                              void* d_out, int out_size) {
    const float* feat  = (const float*)d_in[0];
    const float* coord = (const float*)d_in[1];
    // d_in[2] = adj (unused by forward)
    const float* FCm   = (const float*)d_in[3];
    const float* fc_w  = (const float*)d_in[4];
    const float* fc_b  = (const float*)d_in[5];
    const float* sc_w  = (const float*)d_in[6];
    const float* sc_b  = (const float*)d_in[7];
    const float* lin_w = (const float*)d_in[8];
    const float* lin_b = (const float*)d_in[9];
    float* out = (float*)d_out;

    cudaFuncSetAttribute(k_scores, cudaFuncAttributeMaxDynamicSharedMemorySize,
                         SMEM_SCORES);

    dim3 gf(CV / 64, NV / 16);
    k_fin<<<gf, 128>>>(feat, FCm, lin_w);
    dim3 gs(NV / 64, NV / 64);
    k_scores<<<gs, 256, SMEM_SCORES>>>(coord, fc_w, fc_b, sc_w, sc_b, lin_w, lin_b);
    k_softmax<<<NV / 2, 64>>>();
    dim3 go(CV / 64, NV / 16);
    k_out<<<go, 128>>>(out);
}

// round 6
// speedup vs baseline: 2.0223x; 1.3870x over previous
#include <cuda_runtime.h>

#define NV 768
#define CV 256

typedef unsigned long long ull;

// Scratch (device globals: allocation-free)
__device__ float g_fp[2][NV * CV];      // k_fin split-K partials
__device__ float g_fin[NV * CV];        // f_input
__device__ float g_S[NV];               // S_i = sum_c lw[c]*f_input[i][c]
__device__ float g_Lw;                  // sum of lin_w[0..255]
__device__ float g_att[NV * NV];        // scores, then attention (in place)
__device__ float g_op[8][NV * CV];      // k_out split-K partials

// ---------------- packed f32x2 helpers (sm_103a) ----------------
__device__ __forceinline__ ull f32x2_add(ull a, ull b) {
    ull r; asm("add.rn.f32x2 %0, %1, %2;" : "=l"(r) : "l"(a), "l"(b)); return r;
}
__device__ __forceinline__ ull f32x2_fma(ull a, ull b, ull c) {
    ull r; asm("fma.rn.f32x2 %0, %1, %2, %3;" : "=l"(r) : "l"(a), "l"(b), "l"(c)); return r;
}
__device__ __forceinline__ ull f32x2_abs(ull a) { return a & 0x7FFFFFFF7FFFFFFFULL; }
__device__ __forceinline__ ull f32x2_dup(float v) {
    unsigned u = __float_as_uint(v); return ((ull)u << 32) | (ull)u;
}
__device__ __forceinline__ float f32x2_lo(ull a) { return __uint_as_float((unsigned)a); }
__device__ __forceinline__ float f32x2_hi(ull a) { return __uint_as_float((unsigned)(a >> 32)); }

// ---------------------------------------------------------------------------
// Kernel 1: f_input partials = features @ FC, split-K.
// Tile 32(M)x64(N), 128 threads, acc[4][2]. grid (4, 24, 2) = 192 blocks.
// ---------------------------------------------------------------------------
__global__ void k_fin(const float* __restrict__ feat, const float* __restrict__ FCm) {
    __shared__ ull   sa2[32 * 32];   // feat, value-duplicated pairs (8KB)
    __shared__ float sb[32 * 64];    // FC rows (8KB)

    const int tid = threadIdx.x;     // 128
    const int tx = tid & 15;
    const int ty = tid >> 4;         // 0..7
    const int j0 = blockIdx.x * 64;
    const int i0 = blockIdx.y * 32;
    const int kbase = blockIdx.z * 128;

    ull acc[4][2];
    #pragma unroll
    for (int r = 0; r < 4; r++) { acc[r][0] = 0ull; acc[r][1] = 0ull; }

    for (int s = 0; s < 4; s++) {
        const int k0 = kbase + s * 32;
        #pragma unroll
        for (int q = 0; q < 8; q++) {
            int idx = tid + q * 128;          // 0..1023
            int r = idx >> 5, kc = idx & 31;
            sa2[idx] = f32x2_dup(feat[(i0 + r) * CV + k0 + kc]);
        }
        #pragma unroll
        for (int q = 0; q < 4; q++) {
            int i4 = tid + q * 128;           // 0..511 float4s
            int kc = i4 >> 4, j4 = i4 & 15;
            *(float4*)&sb[kc * 64 + j4 * 4] =
                *(const float4*)&FCm[(k0 + kc) * CV + j0 + j4 * 4];
        }
        __syncthreads();

        #pragma unroll 8
        for (int kc = 0; kc < 32; kc++) {
            ull a_[4], b_[2];
            #pragma unroll
            for (int r = 0; r < 4; r++) a_[r] = sa2[(ty + 8 * r) * 32 + kc];
            #pragma unroll
            for (int m = 0; m < 2; m++) b_[m] = *(const ull*)&sb[kc * 64 + 2 * (tx + 16 * m)];
            #pragma unroll
            for (int r = 0; r < 4; r++)
                #pragma unroll
                for (int m = 0; m < 2; m++)
                    acc[r][m] = f32x2_fma(a_[r], b_[m], acc[r][m]);
        }
        __syncthreads();
    }

    float* dst = g_fp[blockIdx.z];
    #pragma unroll
    for (int r = 0; r < 4; r++) {
        int i = i0 + ty + 8 * r;
        #pragma unroll
        for (int m = 0; m < 2; m++)
            *(ull*)&dst[i * CV + j0 + 2 * (tx + 16 * m)] = acc[r][m];
    }
}

// ---------------------------------------------------------------------------
// Kernel 2: reduce fin partials, compute S_i and Lw. Warp-per-row.
// grid 96, block 256 (8 warps).
// ---------------------------------------------------------------------------
__global__ void k_finred(const float* __restrict__ lin_w) {
    const int w = threadIdx.x >> 5, lane = threadIdx.x & 31;
    const int row = blockIdx.x * 8 + w;
    const int c0 = row * CV + lane * 8;

    float4 x0 = *(const float4*)&g_fp[0][c0];
    float4 x1 = *(const float4*)&g_fp[0][c0 + 4];
    float4 y0 = *(const float4*)&g_fp[1][c0];
    float4 y1 = *(const float4*)&g_fp[1][c0 + 4];
    x0.x += y0.x; x0.y += y0.y; x0.z += y0.z; x0.w += y0.w;
    x1.x += y1.x; x1.y += y1.y; x1.z += y1.z; x1.w += y1.w;
    *(float4*)&g_fin[c0]     = x0;
    *(float4*)&g_fin[c0 + 4] = x1;

    float4 w0_ = *(const float4*)&lin_w[lane * 8];
    float4 w1_ = *(const float4*)&lin_w[lane * 8 + 4];
    float s = x0.x * w0_.x + x0.y * w0_.y + x0.z * w0_.z + x0.w * w0_.w
            + x1.x * w1_.x + x1.y * w1_.y + x1.z * w1_.z + x1.w * w1_.w;
    #pragma unroll
    for (int o = 16; o > 0; o >>= 1) s += __shfl_xor_sync(0xffffffffu, s, o);
    if (lane == 0) g_S[row] = s;

    if (blockIdx.x == 0 && w == 0) {
        float lw = (w0_.x + w0_.y + w0_.z + w0_.w) + (w1_.x + w1_.y + w1_.z + w1_.w);
        #pragma unroll
        for (int o = 16; o > 0; o >>= 1) lw += __shfl_xor_sync(0xffffffffu, lw, o);
        if (lane == 0) g_Lw = lw;
    }
}

// ---------------------------------------------------------------------------
// Kernel 3: scores. 64x64 tile, 256 threads, 4x4 micro, channel-packed f32x2.
// score(i,j) = leaky( 0.6*(P_i+Q_j) + lin_b + sum_c 0.4*lw[c]*|u_i[c]+v_j[c]| )
// ---------------------------------------------------------------------------
#define SROW 258   // 256 + pad(2)
#define SMEM_SCORES ((2 * 64 * SROW + 256 + 2 * 192 + 16) * 4)

__global__ void __launch_bounds__(256, 1) k_scores(
        const float* __restrict__ coord,
        const float* __restrict__ fc_w, const float* __restrict__ fc_b,
        const float* __restrict__ sc_w, const float* __restrict__ sc_b,
        const float* __restrict__ lin_w, const float* __restrict__ lin_b) {
    extern __shared__ float smem[];
    float* su  = smem;                        // [64][SROW]  u = w0*f_i
    float* sv  = smem + 64 * SROW;            // [64][SROW]  v = w1*f_j + bf
    float* slw = smem + 2 * 64 * SROW;        // [256]       0.4*lin_w
    float* scu = slw + 256;                   // [64*3]      sc_w0*coord_i
    float* scv = scu + 192;                   // [64*3]      sc_w1*coord_j + sc_b

    const int tid = threadIdx.x;
    const int tx = tid & 15;
    const int ty = tid >> 4;
    const int i0 = blockIdx.y * 64;
    const int j0 = blockIdx.x * 64;

    const float w0 = fc_w[0], w1 = fc_w[1], bf = fc_b[0];

    {
        const int r = tid >> 2, l4 = tid & 3;
        const float4* gi = (const float4*)&g_fin[(i0 + r) * CV];
        const float4* gj = (const float4*)&g_fin[(j0 + r) * CV];
        float* sur = &su[r * SROW];
        float* svr = &sv[r * SROW];
        #pragma unroll
        for (int q = 0; q < 16; q++) {
            float4 a = gi[l4 + q * 4];
            float4 b = gj[l4 + q * 4];
            int o = (l4 + q * 4) * 4;
            sur[o]     = w0 * a.x; sur[o + 1] = w0 * a.y;
            sur[o + 2] = w0 * a.z; sur[o + 3] = w0 * a.w;
            svr[o]     = fmaf(w1, b.x, bf); svr[o + 1] = fmaf(w1, b.y, bf);
            svr[o + 2] = fmaf(w1, b.z, bf); svr[o + 3] = fmaf(w1, b.w, bf);
        }
        slw[tid] = 0.4f * lin_w[tid];
        if (tid < 192) {
            int rr = tid / 3, k = tid - rr * 3;
            scu[tid] = sc_w[0] * coord[(i0 + rr) * 3 + k];
            scv[tid] = fmaf(sc_w[1], coord[(j0 + rr) * 3 + k], sc_b[0]);
        }
    }
    __syncthreads();

    const float* sup[4];
    const float* svp[4];
    #pragma unroll
    for (int k = 0; k < 4; k++) sup[k] = &su[(ty + 16 * k) * SROW];
    #pragma unroll
    for (int m = 0; m < 4; m++) svp[m] = &sv[(tx + 16 * m) * SROW];

    ull acc[4][4];
    #pragma unroll
    for (int k = 0; k < 4; k++)
        #pragma unroll
        for (int m = 0; m < 4; m++) acc[k][m] = 0ull;

    #pragma unroll 4
    for (int cc = 0; cc < CV; cc += 2) {
        ull w2 = *(const ull*)&slw[cc];
        ull a_[4], b_[4];
        #pragma unroll
        for (int k = 0; k < 4; k++) a_[k] = *(const ull*)&sup[k][cc];
        #pragma unroll
        for (int m = 0; m < 4; m++) b_[m] = *(const ull*)&svp[m][cc];
        #pragma unroll
        for (int k = 0; k < 4; k++)
            #pragma unroll
            for (int m = 0; m < 4; m++) {
                ull t = f32x2_abs(f32x2_add(a_[k], b_[m]));
                acc[k][m] = f32x2_fma(w2, t, acc[k][m]);
            }
    }

    const float lb  = lin_b[0];
    const float Lw  = g_Lw;
    const float lc0 = lin_w[CV], lc1 = lin_w[CV + 1], lc2 = lin_w[CV + 2];
    const float base0 = fmaf(0.6f * bf, Lw, lb);

    float Si[4], Sj[4];
    #pragma unroll
    for (int k = 0; k < 4; k++) Si[k] = g_S[i0 + ty + 16 * k];
    #pragma unroll
    for (int m = 0; m < 4; m++) Sj[m] = g_S[j0 + tx + 16 * m];

    #pragma unroll
    for (int k = 0; k < 4; k++) {
        int ir = ty + 16 * k;
        float cu0 = scu[ir * 3], cu1 = scu[ir * 3 + 1], cu2 = scu[ir * 3 + 2];
        #pragma unroll
        for (int m = 0; m < 4; m++) {
            int jr = tx + 16 * m;
            float t0 = cu0 + scv[jr * 3];
            float t1 = cu1 + scv[jr * 3 + 1];
            float t2 = cu2 + scv[jr * 3 + 2];
            float ct = lc0 * fmaf(0.4f, fabsf(t0), 0.6f * t0)
                     + lc1 * fmaf(0.4f, fabsf(t1), 0.6f * t1)
                     + lc2 * fmaf(0.4f, fabsf(t2), 0.6f * t2);
            float s = fmaf(0.6f, fmaf(w0, Si[k], w1 * Sj[m]), base0) + ct
                      + f32x2_lo(acc[k][m]) + f32x2_hi(acc[k][m]);
            g_att[(i0 + ir) * NV + (j0 + jr)] = fmaxf(s, 0.2f * s);   // leaky(0.2)
        }
    }
}

// ---------------------------------------------------------------------------
// Kernel 4: row softmax. grid 384, block 64 (2 warps, warp-per-row).
// ---------------------------------------------------------------------------
__global__ void k_softmax() {
    const int w = threadIdx.x >> 5, lane = threadIdx.x & 31;
    const int row = blockIdx.x * 2 + w;
    float4* p = (float4*)&g_att[row * NV];   // 192 float4 per row

    float4 x[6];
    #pragma unroll
    for (int l = 0; l < 6; l++) x[l] = p[lane + 32 * l];

    float m = -1e30f;
    #pragma unroll
    for (int l = 0; l < 6; l++)
        m = fmaxf(m, fmaxf(fmaxf(x[l].x, x[l].y), fmaxf(x[l].z, x[l].w)));
    #pragma unroll
    for (int s = 16; s > 0; s >>= 1) m = fmaxf(m, __shfl_xor_sync(0xffffffffu, m, s));

    float sum = 0.f;
    #pragma unroll
    for (int l = 0; l < 6; l++) {
        x[l].x = __expf(x[l].x - m); x[l].y = __expf(x[l].y - m);
        x[l].z = __expf(x[l].z - m); x[l].w = __expf(x[l].w - m);
        sum += (x[l].x + x[l].y) + (x[l].z + x[l].w);
    }
    #pragma unroll
    for (int s = 16; s > 0; s >>= 1) sum += __shfl_xor_sync(0xffffffffu, sum, s);
    float inv = 1.0f / sum;

    #pragma unroll
    for (int l = 0; l < 6; l++) {
        x[l].x *= inv; x[l].y *= inv; x[l].z *= inv; x[l].w *= inv;
        p[lane + 32 * l] = x[l];
    }
}

// ---------------------------------------------------------------------------
// Kernel 5: out partials = attention @ f_input, split-K (8 ways).
// Tile 32(M)x128(N), 128 threads, acc[4][4]. grid (2, 24, 8) = 384 blocks.
// ---------------------------------------------------------------------------
__global__ void k_out_mm() {
    __shared__ ull   sa2[32 * 32];    // attention, value-duplicated pairs (8KB)
    __shared__ float sb[32 * 128];    // f_input rows (16KB)

    const int tid = threadIdx.x;      // 128
    const int tx = tid & 15;
    const int ty = tid >> 4;          // 0..7
    const int j0 = blockIdx.x * 128;
    const int i0 = blockIdx.y * 32;
    const int kbase = blockIdx.z * 96;

    ull acc[4][4];
    #pragma unroll
    for (int r = 0; r < 4; r++)
        #pragma unroll
        for (int m = 0; m < 4; m++) acc[r][m] = 0ull;

    for (int s = 0; s < 3; s++) {
        const int k0 = kbase + s * 32;
        #pragma unroll
        for (int q = 0; q < 8; q++) {
            int idx = tid + q * 128;           // 0..1023
            int r = idx >> 5, kc = idx & 31;
            sa2[idx] = f32x2_dup(g_att[(i0 + r) * NV + k0 + kc]);
        }
        #pragma unroll
        for (int q = 0; q < 8; q++) {
            int i4 = tid + q * 128;            // 0..1023 float4s
            int kc = i4 >> 5, j4 = i4 & 31;
            *(float4*)&sb[kc * 128 + j4 * 4] =
                *(const float4*)&g_fin[(k0 + kc) * CV + j0 + j4 * 4];
        }
        __syncthreads();

        #pragma unroll 8
        for (int kc = 0; kc < 32; kc++) {
            ull a_[4], b_[4];
            #pragma unroll
            for (int r = 0; r < 4; r++) a_[r] = sa2[(ty + 8 * r) * 32 + kc];
            #pragma unroll
            for (int m = 0; m < 4; m++) b_[m] = *(const ull*)&sb[kc * 128 + 2 * (tx + 16 * m)];
            #pragma unroll
            for (int r = 0; r < 4; r++)
                #pragma unroll
                for (int m = 0; m < 4; m++)
                    acc[r][m] = f32x2_fma(a_[r], b_[m], acc[r][m]);
        }
        __syncthreads();
    }

    float* dst = g_op[blockIdx.z];
    #pragma unroll
    for (int r = 0; r < 4; r++) {
        int i = i0 + ty + 8 * r;
        #pragma unroll
        for (int m = 0; m < 4; m++)
            *(ull*)&dst[i * CV + j0 + 2 * (tx + 16 * m)] = acc[r][m];
    }
}

// ---------------------------------------------------------------------------
// Kernel 6: reduce out partials + ELU. Warp-per-row. grid 96, block 256.
// ---------------------------------------------------------------------------
__global__ void k_outred(float* __restrict__ out) {
    const int w = threadIdx.x >> 5, lane = threadIdx.x & 31;
    const int row = blockIdx.x * 8 + w;
    const int c0 = row * CV + lane * 8;

    float4 s0 = make_float4(0.f, 0.f, 0.f, 0.f);
    float4 s1 = make_float4(0.f, 0.f, 0.f, 0.f);
    #pragma unroll
    for (int p = 0; p < 8; p++) {
        float4 a = *(const float4*)&g_op[p][c0];
        float4 b = *(const float4*)&g_op[p][c0 + 4];
        s0.x += a.x; s0.y += a.y; s0.z += a.z; s0.w += a.w;
        s1.x += b.x; s1.y += b.y; s1.z += b.z; s1.w += b.w;
    }
    s0.x = (s0.x > 0.f) ? s0.x : (__expf(s0.x) - 1.f);
    s0.y = (s0.y > 0.f) ? s0.y : (__expf(s0.y) - 1.f);
    s0.z = (s0.z > 0.f) ? s0.z : (__expf(s0.z) - 1.f);
    s0.w = (s0.w > 0.f) ? s0.w : (__expf(s0.w) - 1.f);
    s1.x = (s1.x > 0.f) ? s1.x : (__expf(s1.x) - 1.f);
    s1.y = (s1.y > 0.f) ? s1.y : (__expf(s1.y) - 1.f);
    s1.z = (s1.z > 0.f) ? s1.z : (__expf(s1.z) - 1.f);
    s1.w = (s1.w > 0.f) ? s1.w : (__expf(s1.w) - 1.f);
    *(float4*)&out[c0]     = s0;
    *(float4*)&out[c0 + 4] = s1;
}

// ---------------------------------------------------------------------------
extern "C" void kernel_launch(void* const* d_in, const int* in_sizes, int n_in,
                              void* d_out, int out_size) {
    const float* feat  = (const float*)d_in[0];
    const float* coord = (const float*)d_in[1];
    // d_in[2] = adj (unused by forward)
    const float* FCm   = (const float*)d_in[3];
    const float* fc_w  = (const float*)d_in[4];
    const float* fc_b  = (const float*)d_in[5];
    const float* sc_w  = (const float*)d_in[6];
    const float* sc_b  = (const float*)d_in[7];
    const float* lin_w = (const float*)d_in[8];
    const float* lin_b = (const float*)d_in[9];
    float* out = (float*)d_out;

    cudaFuncSetAttribute(k_scores, cudaFuncAttributeMaxDynamicSharedMemorySize,
                         SMEM_SCORES);

    k_fin<<<dim3(4, 24, 2), 128>>>(feat, FCm);
    k_finred<<<96, 256>>>(lin_w);
    k_scores<<<dim3(12, 12), 256, SMEM_SCORES>>>(coord, fc_w, fc_b, sc_w, sc_b, lin_w, lin_b);
    k_softmax<<<NV / 2, 64>>>();
    k_out_mm<<<dim3(2, 24, 8), 128>>>();
    k_outred<<<96, 256>>>(out);
}